// round 1
// baseline (speedup 1.0000x reference)
#include <cuda_runtime.h>
#include <math.h>
#include <stdint.h>

#define NN 50000
#define NE 800000
#define D  128
#define DE 16
#define G4 512   // 4*D gates

// ---------------- scratch (static device globals; no allocation) ----------------
__device__ __align__(16) float g_W[2 * D * D];        // evolving LSTM state (hs) per layer
__device__ __align__(16) float g_G0[2 * D * G4];      // precomputed Wih@x + b per layer
__device__ __align__(16) float g_WihT[2 * D * G4];    // transposed Wih for coalesced G0 GEMM
__device__ __align__(16) float g_ft[(size_t)NN * D];  // nf @ W
__device__ __align__(16) float g_feat[(size_t)NN * D];// layer-0 GAT output (post leaky)
__device__ __align__(16) float g_out[(size_t)NN * D]; // aggregation accumulator
__device__ float    g_sc[NE];      // edge score, then overwritten with exp
__device__ float    g_ssrc[NN];
__device__ float    g_sdst[NN];
__device__ float    g_den[NN];
__device__ unsigned g_mx[NN];      // ordered-int encoded segment max

// ordered-int encoding for float atomicMax
__device__ __forceinline__ unsigned fenc(float f) {
    unsigned u = __float_as_uint(f);
    return (u & 0x80000000u) ? ~u : (u | 0x80000000u);
}
__device__ __forceinline__ float fdec(unsigned e) {
    return (e & 0x80000000u) ? __uint_as_float(e ^ 0x80000000u) : __uint_as_float(~e);
}

// ---------------- LSTM ----------------

// transpose Wih (L,512,128) -> WihT (L,128,512) for coalesced reads in G0
__global__ void k_transpose_wih(const float* __restrict__ Wih) {
    int idx = blockIdx.x * 256 + threadIdx.x;
    if (idx >= 2 * G4 * D) return;
    int layer = idx / (G4 * D);
    int rem   = idx - layer * (G4 * D);
    int g = rem / D, k = rem % D;
    g_WihT[(size_t)layer * (D * G4) + k * G4 + g] = Wih[idx];
}

// G0[t][g] = b[g] + sum_k X[t][k] * Wih[g][k]   (X = W0 or current state)
__global__ void __launch_bounds__(512) k_lstm_g0(
    const float* __restrict__ Xext, int use_state,
    const float* __restrict__ bih, const float* __restrict__ bhh)
{
    int t = blockIdx.x, layer = blockIdx.y;
    int g = threadIdx.x;
    __shared__ float xs[D];
    const float* X = use_state ? (g_W + layer * D * D) : (Xext + layer * D * D);
    if (g < D) xs[g] = X[t * D + g];
    __syncthreads();
    const float* wt = g_WihT + (size_t)layer * (D * G4);
    float acc = bih[layer * G4 + g] + bhh[layer * G4 + g];
#pragma unroll 8
    for (int k = 0; k < D; k++)
        acc = fmaf(wt[k * G4 + g], xs[k], acc);
    g_G0[(size_t)(layer * D + t) * G4 + g] = acc;
}

// 128-step recurrence, one CTA per layer (grid=2). Whh: k[0:96) in smem
// (interleaved float4 layout, conflict-free), k[96:128) in registers.
__global__ void __launch_bounds__(512, 1) k_lstm_rec(const float* __restrict__ Whh)
{
    int layer = blockIdx.x;
    extern __shared__ float sh[];
    float4* wsm = (float4*)sh;           // 24*512 float4 = 192KB
    float*  hsm = sh + 24 * 512 * 4;     // 128 floats
    float*  gsm = hsm + 128;             // 512 floats
    int r = threadIdx.x;

    const float4* wrow = (const float4*)(Whh + (size_t)(layer * G4 + r) * D);
    float4 wr[8];
#pragma unroll
    for (int k4 = 0; k4 < 24; k4++) wsm[k4 * 512 + r] = wrow[k4];
#pragma unroll
    for (int i = 0; i < 8; i++) wr[i] = wrow[24 + i];
    if (r < D) hsm[r] = 0.f;
    float c = 0.f;
    const float* g0 = g_G0 + (size_t)layer * (D * G4);
    float* ws = g_W + layer * D * D;
    __syncthreads();

    for (int t = 0; t < D; t++) {
        float acc = g0[t * G4 + r];
        const float4* h4 = (const float4*)hsm;
#pragma unroll
        for (int k4 = 0; k4 < 24; k4++) {
            float4 w = wsm[k4 * 512 + r];
            float4 h = h4[k4];
            acc = fmaf(w.x, h.x, acc); acc = fmaf(w.y, h.y, acc);
            acc = fmaf(w.z, h.z, acc); acc = fmaf(w.w, h.w, acc);
        }
#pragma unroll
        for (int i = 0; i < 8; i++) {
            float4 w = wr[i]; float4 h = h4[24 + i];
            acc = fmaf(w.x, h.x, acc); acc = fmaf(w.y, h.y, acc);
            acc = fmaf(w.z, h.z, acc); acc = fmaf(w.w, h.w, acc);
        }
        // gate order: i, f, g, o ; g uses tanh, others sigmoid
        float a = (r >= 256 && r < 384) ? tanhf(acc) : (1.f / (1.f + expf(-acc)));
        gsm[r] = a;
        __syncthreads();
        if (r < D) {
            float iv = gsm[r], fv = gsm[r + 128], gv = gsm[r + 256], ov = gsm[r + 384];
            c = fmaf(fv, c, iv * gv);
            float h = ov * tanhf(c);
            hsm[r] = h;
            ws[t * D + r] = h;   // hs row t
        }
        __syncthreads();
    }
}

// ---------------- GAT ----------------

__global__ void k_init() {
    int idx = blockIdx.x * 256 + threadIdx.x;
    if (idx < NN * D) g_out[idx] = 0.f;
    if (idx < NN) { g_mx[idx] = 0u; g_den[idx] = 0.f; }
}

// ft = nf @ W ; s_src = nf @ a_src ; s_dst = nf @ a_dst. Warp-per-row, W in smem.
__global__ void __launch_bounds__(256) k_gat_gemm(
    const float* __restrict__ nf_ext, int layer, const float* __restrict__ a_w)
{
    extern __shared__ float sh[];
    float* Wsm  = sh;              // 128*128
    float* av   = sh + D * D;      // a_src[128], a_dst[128]
    float* xbuf = av + 2 * D;      // 8 warps * 128
    int tid = threadIdx.x;
    const float* Wg = g_W + layer * D * D;
    for (int i = tid; i < D * D; i += 256) Wsm[i] = Wg[i];
    const float* aw = a_w + layer * (2 * D + DE);
    if (tid < D) { av[tid] = aw[tid]; av[D + tid] = aw[D + DE + tid]; }
    __syncthreads();

    const float* nf = layer ? g_feat : nf_ext;
    int warp = tid >> 5, lane = tid & 31;
    int row = blockIdx.x * 8 + warp;
    if (row >= NN) return;

    float* xb = xbuf + warp * D;
    float4 x = ((const float4*)(nf + (size_t)row * D))[lane];
    ((float4*)xb)[lane] = x;
    __syncwarp();

    float ss = x.x * av[lane * 4] + x.y * av[lane * 4 + 1]
             + x.z * av[lane * 4 + 2] + x.w * av[lane * 4 + 3];
    float sd = x.x * av[D + lane * 4] + x.y * av[D + lane * 4 + 1]
             + x.z * av[D + lane * 4 + 2] + x.w * av[D + lane * 4 + 3];

    float4 acc = make_float4(0.f, 0.f, 0.f, 0.f);
    const float4* W4  = (const float4*)Wsm;
    const float4* xb4 = (const float4*)xb;
#pragma unroll 8
    for (int k4 = 0; k4 < 32; k4++) {
        float4 xk = xb4[k4];
        float4 w;
        w = W4[(k4 * 4 + 0) * 32 + lane];
        acc.x = fmaf(xk.x, w.x, acc.x); acc.y = fmaf(xk.x, w.y, acc.y);
        acc.z = fmaf(xk.x, w.z, acc.z); acc.w = fmaf(xk.x, w.w, acc.w);
        w = W4[(k4 * 4 + 1) * 32 + lane];
        acc.x = fmaf(xk.y, w.x, acc.x); acc.y = fmaf(xk.y, w.y, acc.y);
        acc.z = fmaf(xk.y, w.z, acc.z); acc.w = fmaf(xk.y, w.w, acc.w);
        w = W4[(k4 * 4 + 2) * 32 + lane];
        acc.x = fmaf(xk.z, w.x, acc.x); acc.y = fmaf(xk.z, w.y, acc.y);
        acc.z = fmaf(xk.z, w.z, acc.z); acc.w = fmaf(xk.z, w.w, acc.w);
        w = W4[(k4 * 4 + 3) * 32 + lane];
        acc.x = fmaf(xk.w, w.x, acc.x); acc.y = fmaf(xk.w, w.y, acc.y);
        acc.z = fmaf(xk.w, w.z, acc.z); acc.w = fmaf(xk.w, w.w, acc.w);
    }
    ((float4*)(g_ft + (size_t)row * D))[lane] = acc;

#pragma unroll
    for (int o = 16; o; o >>= 1) {
        ss += __shfl_down_sync(0xffffffffu, ss, o);
        sd += __shfl_down_sync(0xffffffffu, sd, o);
    }
    if (lane == 0) { g_ssrc[row] = ss; g_sdst[row] = sd; }
}

__global__ void __launch_bounds__(256) k_edge_score(
    const int* __restrict__ src, const int* __restrict__ dst,
    const float* __restrict__ ef, const float* __restrict__ a_w,
    int layer, int n_edges)
{
    int e = blockIdx.x * 256 + threadIdx.x;
    if (e >= n_edges) return;
    const float* ae = a_w + layer * (2 * D + DE) + D;
    int s = src[e], d = dst[e];
    const float4* ep = (const float4*)(ef + (size_t)e * DE);
    float sc = g_ssrc[s] + g_sdst[d];
#pragma unroll
    for (int i = 0; i < 4; i++) {
        float4 v = ep[i];
        sc += v.x * __ldg(ae + i * 4) + v.y * __ldg(ae + i * 4 + 1)
            + v.z * __ldg(ae + i * 4 + 2) + v.w * __ldg(ae + i * 4 + 3);
    }
    g_sc[e] = sc;
    atomicMax(&g_mx[d], fenc(sc));
}

__global__ void __launch_bounds__(256) k_edge_exp(const int* __restrict__ dst, int n_edges)
{
    int e = blockIdx.x * 256 + threadIdx.x;
    if (e >= n_edges) return;
    int d = dst[e];
    float ex = expf(g_sc[e] - fdec(g_mx[d]));
    g_sc[e] = ex;
    atomicAdd(&g_den[d], ex);
}

// one warp per edge: gather ft[src] (L2-resident), scale by alpha, v4 reduce into out[dst]
__global__ void __launch_bounds__(256) k_aggregate(
    const int* __restrict__ src, const int* __restrict__ dst, int n_edges)
{
    int gw = (blockIdx.x * 256 + threadIdx.x) >> 5;
    int lane = threadIdx.x & 31;
    if (gw >= n_edges) return;
    int s = 0, d = 0; float al = 0.f;
    if (lane == 0) {
        s = src[gw]; d = dst[gw];
        al = g_sc[gw] / g_den[d];
    }
    s  = __shfl_sync(0xffffffffu, s, 0);
    d  = __shfl_sync(0xffffffffu, d, 0);
    al = __shfl_sync(0xffffffffu, al, 0);
    float4 v = ((const float4*)(g_ft + (size_t)s * D))[lane];
    float* p = g_out + (size_t)d * D + lane * 4;
    asm volatile("red.global.add.v4.f32 [%0], {%1,%2,%3,%4};"
                 :: "l"(p), "f"(v.x * al), "f"(v.y * al), "f"(v.z * al), "f"(v.w * al)
                 : "memory");
}

__global__ void __launch_bounds__(256) k_finalize(float* __restrict__ dest_ext, int to_internal)
{
    int idx = blockIdx.x * 256 + threadIdx.x;
    if (idx >= NN * D) return;
    float v = g_out[idx];
    v = v >= 0.f ? v : 0.01f * v;   // leaky_relu, slope 0.01
    if (to_internal) g_feat[idx] = v;
    else dest_ext[idx] = v;
}

// ---------------- launch ----------------
extern "C" void kernel_launch(void* const* d_in, const int* in_sizes, int n_in,
                              void* d_out, int out_size)
{
    const int*   src     = (const int*)  d_in[0];
    const int*   dst     = (const int*)  d_in[1];
    const float* n_feats = (const float*)d_in[2];
    const float* e_feats = (const float*)d_in[3];
    const float* W0      = (const float*)d_in[4];
    const float* Wih     = (const float*)d_in[5];
    const float* Whh     = (const float*)d_in[6];
    const float* bih     = (const float*)d_in[7];
    const float* bhh     = (const float*)d_in[8];
    const float* a_w     = (const float*)d_in[9];

    int n_edges = in_sizes[0] / 3;        // 800000
    int n_nodes = in_sizes[2] / (3 * D);  // 50000

    int smem_rec  = (24 * 512 * 4 + 128 + 512) * (int)sizeof(float);   // ~194.5KB
    int smem_gemm = (D * D + 2 * D + 8 * D) * (int)sizeof(float);      // ~70.5KB
    cudaFuncSetAttribute(k_lstm_rec, cudaFuncAttributeMaxDynamicSharedMemorySize, smem_rec);
    cudaFuncSetAttribute(k_gat_gemm, cudaFuncAttributeMaxDynamicSharedMemorySize, smem_gemm);

    // only timestep j=2 matters for the output (feats never mix across j)
    const int*   src2 = src + 2 * n_edges;
    const int*   dst2 = dst + 2 * n_edges;
    const float* nf2  = n_feats + (size_t)2 * n_nodes * D;
    const float* ef2  = e_feats + (size_t)2 * n_edges * DE;

    // LSTM chains for both layers run concurrently (grid.y / grid.x = 2)
    k_transpose_wih<<<(2 * G4 * D + 255) / 256, 256>>>(Wih);
    for (int call = 0; call < 3; call++) {
        k_lstm_g0<<<dim3(D, 2), 512>>>(W0, call > 0, bih, bhh);
        k_lstm_rec<<<2, 512, smem_rec>>>(Whh);
    }

    for (int layer = 0; layer < 2; layer++) {
        k_init<<<(n_nodes * D + 255) / 256, 256>>>();
        k_gat_gemm<<<(n_nodes + 7) / 8, 256, smem_gemm>>>(nf2, layer, a_w);
        k_edge_score<<<(n_edges + 255) / 256, 256>>>(src2, dst2, ef2, a_w, layer, n_edges);
        k_edge_exp<<<(n_edges + 255) / 256, 256>>>(dst2, n_edges);
        k_aggregate<<<(n_edges * 32 + 255) / 256, 256>>>(src2, dst2, n_edges);
        k_finalize<<<(n_nodes * D + 255) / 256, 256>>>((float*)d_out, layer == 0);
    }
}